// round 3
// baseline (speedup 1.0000x reference)
#include <cuda_runtime.h>
#include <cuda_bf16.h>

// RetinaFace decode, N = 1e6 priors. 2 priors per thread, streaming cache hints.
// Output layout (float32):
//   [0    , 4N )  boxes_m    (N,4)
//   [4N   , 5N )  conf_m     (N,)
//   [5N   , 6N )  pred_m     (N,)  == 0 always (2-class)
//   [6N   , 22N)  detections (1,N,16)
//   [22N  , 23N)  keep       (N,)

struct PriorOut {
    float4 box;     // masked box
    float  confm;   // masked conf
    float  mf;      // keep as 0/1
    float4 d1, d2, d3;  // det rows 1..3 (row0 == box)
};

__device__ __forceinline__ PriorOut decode_one(
    float4 a, float4 b, float4 c, float4 d, float4 p,
    float v0, float v1, float th)
{
    // 2-class softmax: conf = max prob; pred==1 iff c1 > c0 (argmax tie -> 0)
    float m  = fmaxf(b.x, b.y);
    float e0 = __expf(b.x - m);
    float e1 = __expf(b.y - m);
    float conf = fmaxf(e0, e1) / (e0 + e1);
    bool  keep = (b.y > b.x) && (conf > th);
    float mf   = keep ? 1.0f : 0.0f;

    // box decode
    float cx = p.x + a.x * v0 * p.z;
    float cy = p.y + a.y * v0 * p.w;
    float w  = p.z * __expf(a.z * v1);
    float h  = p.w * __expf(a.w * v1);
    float x0 = cx - 0.5f * w;
    float y0 = cy - 0.5f * h;
    float x1 = x0 + w;
    float y1 = y0 + h;

    // landmarks
    float sx = v0 * p.z, sy = v0 * p.w;
    float l0x = p.x + b.z * sx, l0y = p.y + b.w * sy;
    float l1x = p.x + c.x * sx, l1y = p.y + c.y * sy;
    float l2x = p.x + c.z * sx, l2y = p.y + c.w * sy;
    float l3x = p.x + d.x * sx, l3y = p.y + d.y * sy;
    float l4x = p.x + d.z * sx, l4y = p.y + d.w * sy;

    PriorOut o;
    o.box   = make_float4(x0 * mf, y0 * mf, x1 * mf, y1 * mf);
    o.confm = conf * mf;
    o.mf    = mf;
    o.d1 = make_float4(o.confm, 0.0f, l0x * mf, l0y * mf);
    o.d2 = make_float4(l1x * mf, l1y * mf, l2x * mf, l2y * mf);
    o.d3 = make_float4(l3x * mf, l3y * mf, l4x * mf, l4y * mf);
    return o;
}

__global__ __launch_bounds__(256) void retina_decode_kernel(
    const float4* __restrict__ in,      // [N,16] as float4[4N]
    const float4* __restrict__ priors,  // [N] float4
    const float* __restrict__ thr,
    const float* __restrict__ var,
    float* __restrict__ out,
    int N)
{
    int t  = blockIdx.x * blockDim.x + threadIdx.x;
    int i0 = 2 * t;
    if (i0 >= N) return;

    const float v0 = var[0];
    const float v1 = var[1];
    const float th = thr[0];

    // Front-batch all 10 loads (MLP)
    const float4* ip = in + (size_t)4 * i0;
    float4 a0 = __ldcs(ip + 0);
    float4 b0 = __ldcs(ip + 1);
    float4 c0 = __ldcs(ip + 2);
    float4 d0 = __ldcs(ip + 3);
    float4 a1 = __ldcs(ip + 4);
    float4 b1 = __ldcs(ip + 5);
    float4 c1 = __ldcs(ip + 6);
    float4 d1 = __ldcs(ip + 7);
    float4 p0 = __ldcs(priors + i0);
    float4 p1 = __ldcs(priors + i0 + 1);

    PriorOut r0 = decode_one(a0, b0, c0, d0, p0, v0, v1, th);
    PriorOut r1 = decode_one(a1, b1, c1, d1, p1, v0, v1, th);

    size_t Ns = (size_t)N;

    // boxes_m [N,4]
    float4* boxp = reinterpret_cast<float4*>(out);
    __stcs(boxp + i0,     r0.box);
    __stcs(boxp + i0 + 1, r1.box);

    // conf_m / pred_m / keep as float2 per thread
    __stcs(reinterpret_cast<float2*>(out + 4 * Ns)  + t, make_float2(r0.confm, r1.confm));
    __stcs(reinterpret_cast<float2*>(out + 5 * Ns)  + t, make_float2(0.0f, 0.0f));
    __stcs(reinterpret_cast<float2*>(out + 22 * Ns) + t, make_float2(r0.mf, r1.mf));

    // detections [N,16]
    float4* det = reinterpret_cast<float4*>(out + 6 * Ns) + (size_t)4 * i0;
    __stcs(det + 0, r0.box);
    __stcs(det + 1, r0.d1);
    __stcs(det + 2, r0.d2);
    __stcs(det + 3, r0.d3);
    __stcs(det + 4, r1.box);
    __stcs(det + 5, r1.d1);
    __stcs(det + 6, r1.d2);
    __stcs(det + 7, r1.d3);
}

extern "C" void kernel_launch(void* const* d_in, const int* in_sizes, int n_in,
                              void* d_out, int out_size)
{
    const float4* in     = (const float4*)d_in[0];
    const float*  thr    = (const float*)d_in[1];
    const float4* priors = (const float4*)d_in[2];
    const float*  var    = (const float*)d_in[3];
    float* out = (float*)d_out;

    int N = in_sizes[2] / 4;  // priors is [N,4]

    int threads = 256;
    int pairs   = (N + 1) / 2;
    int blocks  = (pairs + threads - 1) / threads;
    retina_decode_kernel<<<blocks, threads>>>(in, priors, thr, var, out, N);
}

// round 4
// speedup vs baseline: 1.2882x; 1.2882x over previous
#include <cuda_runtime.h>
#include <cuda_bf16.h>

// RetinaFace decode, N = 1e6 priors.
// 2 priors per thread, SPLIT-STRIDE pairing (t and t+H) so every memory
// instruction keeps consecutive-thread addressing (full coalescing),
// while per-thread MLP doubles to 10 front-batched loads.
//
// Output layout (float32):
//   [0    , 4N )  boxes_m    (N,4)
//   [4N   , 5N )  conf_m     (N,)
//   [5N   , 6N )  pred_m     (N,)  == 0 always (2-class)
//   [6N   , 22N)  detections (1,N,16)
//   [22N  , 23N)  keep       (N,)

struct PriorOut {
    float4 box;
    float  confm;
    float  mf;
    float4 d1, d2, d3;
};

__device__ __forceinline__ PriorOut decode_one(
    float4 a, float4 b, float4 c, float4 d, float4 p,
    float v0, float v1, float th)
{
    // 2-class softmax: conf = max prob; pred==1 iff c1 > c0 (argmax tie -> 0)
    float m  = fmaxf(b.x, b.y);
    float e0 = __expf(b.x - m);
    float e1 = __expf(b.y - m);
    float conf = fmaxf(e0, e1) / (e0 + e1);
    bool  keep = (b.y > b.x) && (conf > th);
    float mf   = keep ? 1.0f : 0.0f;

    float cx = p.x + a.x * v0 * p.z;
    float cy = p.y + a.y * v0 * p.w;
    float w  = p.z * __expf(a.z * v1);
    float h  = p.w * __expf(a.w * v1);
    float x0 = cx - 0.5f * w;
    float y0 = cy - 0.5f * h;
    float x1 = x0 + w;
    float y1 = y0 + h;

    float sx = v0 * p.z, sy = v0 * p.w;
    float l0x = p.x + b.z * sx, l0y = p.y + b.w * sy;
    float l1x = p.x + c.x * sx, l1y = p.y + c.y * sy;
    float l2x = p.x + c.z * sx, l2y = p.y + c.w * sy;
    float l3x = p.x + d.x * sx, l3y = p.y + d.y * sy;
    float l4x = p.x + d.z * sx, l4y = p.y + d.w * sy;

    PriorOut o;
    o.box   = make_float4(x0 * mf, y0 * mf, x1 * mf, y1 * mf);
    o.confm = conf * mf;
    o.mf    = mf;
    o.d1 = make_float4(o.confm, 0.0f, l0x * mf, l0y * mf);
    o.d2 = make_float4(l1x * mf, l1y * mf, l2x * mf, l2y * mf);
    o.d3 = make_float4(l3x * mf, l3y * mf, l4x * mf, l4y * mf);
    return o;
}

__device__ __forceinline__ void write_one(
    float* __restrict__ out, size_t Ns, int i, const PriorOut& r)
{
    reinterpret_cast<float4*>(out)[i] = r.box;      // boxes_m
    out[4 * Ns + i]  = r.confm;                     // conf_m
    out[5 * Ns + i]  = 0.0f;                        // pred_m (always 0)
    out[22 * Ns + i] = r.mf;                        // keep
    float4* det = reinterpret_cast<float4*>(out + 6 * Ns) + (size_t)4 * i;
    det[0] = r.box;
    det[1] = r.d1;
    det[2] = r.d2;
    det[3] = r.d3;
}

__global__ __launch_bounds__(256) void retina_decode_kernel(
    const float4* __restrict__ in,      // [N,16] as float4[4N]
    const float4* __restrict__ priors,  // [N] float4
    const float* __restrict__ thr,
    const float* __restrict__ var,
    float* __restrict__ out,
    int N, int H)
{
    int t = blockIdx.x * blockDim.x + threadIdx.x;
    if (t >= H) return;
    int j = t + H;              // second prior (may be >= N for odd tail)
    bool has2 = (j < N);

    const float v0 = var[0];
    const float v1 = var[1];
    const float th = thr[0];

    // Front-batch all independent loads (MLP = 10)
    const float4* ip0 = in + (size_t)4 * t;
    const float4* ip1 = in + (size_t)4 * j;
    float4 a0 = ip0[0];
    float4 b0 = ip0[1];
    float4 c0 = ip0[2];
    float4 d0 = ip0[3];
    float4 p0 = priors[t];
    float4 a1, b1, c1, d1, p1;
    if (has2) {
        a1 = ip1[0];
        b1 = ip1[1];
        c1 = ip1[2];
        d1 = ip1[3];
        p1 = priors[j];
    }

    PriorOut r0 = decode_one(a0, b0, c0, d0, p0, v0, v1, th);
    size_t Ns = (size_t)N;
    write_one(out, Ns, t, r0);

    if (has2) {
        PriorOut r1 = decode_one(a1, b1, c1, d1, p1, v0, v1, th);
        write_one(out, Ns, j, r1);
    }
}

extern "C" void kernel_launch(void* const* d_in, const int* in_sizes, int n_in,
                              void* d_out, int out_size)
{
    const float4* in     = (const float4*)d_in[0];
    const float*  thr    = (const float*)d_in[1];
    const float4* priors = (const float4*)d_in[2];
    const float*  var    = (const float*)d_in[3];
    float* out = (float*)d_out;

    int N = in_sizes[2] / 4;   // priors is [N,4]
    int H = (N + 1) / 2;       // first-half size; thread t does t and t+H

    int threads = 256;
    int blocks  = (H + threads - 1) / threads;
    retina_decode_kernel<<<blocks, threads>>>(in, priors, thr, var, out, N, H);
}

// round 5
// speedup vs baseline: 1.2941x; 1.0046x over previous
#include <cuda_runtime.h>
#include <cuda_bf16.h>

// RetinaFace decode, N = 1e6 priors. R1 structure (1 prior/thread, fully
// coalesced) + cache policy: loads L2-only (__ldcg), stores streaming (__stcs)
// so the 92MB write stream doesn't evict the 80MB input stream from L2
// across graph replays.
//
// Output layout (float32):
//   [0    , 4N )  boxes_m    (N,4)
//   [4N   , 5N )  conf_m     (N,)
//   [5N   , 6N )  pred_m     (N,)  == 0 always (2-class)
//   [6N   , 22N)  detections (1,N,16)
//   [22N  , 23N)  keep       (N,)

__global__ __launch_bounds__(256) void retina_decode_kernel(
    const float4* __restrict__ in,      // [N,16] as float4[4N]
    const float4* __restrict__ priors,  // [N] float4
    const float* __restrict__ thr,
    const float* __restrict__ var,
    float* __restrict__ out,
    int N)
{
    int i = blockIdx.x * blockDim.x + threadIdx.x;
    if (i >= N) return;

    const float v0 = var[0];
    const float v1 = var[1];
    const float th = thr[0];

    const float4* ip = in + (size_t)4 * i;
    float4 a = __ldcg(ip + 0);  // loc deltas
    float4 b = __ldcg(ip + 1);  // c0, c1, lm0x, lm0y
    float4 c = __ldcg(ip + 2);  // lm1..lm2
    float4 d = __ldcg(ip + 3);  // lm3..lm4
    float4 p = __ldcg(priors + i);

    // 2-class softmax: conf = max prob; pred==1 iff c1 > c0 (argmax tie -> 0)
    float m  = fmaxf(b.x, b.y);
    float e0 = __expf(b.x - m);
    float e1 = __expf(b.y - m);
    float conf = fmaxf(e0, e1) / (e0 + e1);
    bool  keep = (b.y > b.x) && (conf > th);
    float mf   = keep ? 1.0f : 0.0f;

    // box decode
    float cx = p.x + a.x * v0 * p.z;
    float cy = p.y + a.y * v0 * p.w;
    float w  = p.z * __expf(a.z * v1);
    float h  = p.w * __expf(a.w * v1);
    float x0 = cx - 0.5f * w;
    float y0 = cy - 0.5f * h;
    float x1 = x0 + w;
    float y1 = y0 + h;

    // landmarks
    float sx = v0 * p.z, sy = v0 * p.w;
    float l0x = p.x + b.z * sx, l0y = p.y + b.w * sy;
    float l1x = p.x + c.x * sx, l1y = p.y + c.y * sy;
    float l2x = p.x + c.z * sx, l2y = p.y + c.w * sy;
    float l3x = p.x + d.x * sx, l3y = p.y + d.y * sy;
    float l4x = p.x + d.z * sx, l4y = p.y + d.w * sy;

    float4 box  = make_float4(x0 * mf, y0 * mf, x1 * mf, y1 * mf);
    float confm = conf * mf;

    size_t Ns = (size_t)N;

    __stcs(reinterpret_cast<float4*>(out) + i, box);   // boxes_m
    __stcs(out + 4 * Ns + i, confm);                   // conf_m
    __stcs(out + 5 * Ns + i, 0.0f);                    // pred_m (always 0)
    __stcs(out + 22 * Ns + i, mf);                     // keep

    float4* det = reinterpret_cast<float4*>(out + 6 * Ns) + (size_t)4 * i;
    __stcs(det + 0, box);
    __stcs(det + 1, make_float4(confm, 0.0f, l0x * mf, l0y * mf));
    __stcs(det + 2, make_float4(l1x * mf, l1y * mf, l2x * mf, l2y * mf));
    __stcs(det + 3, make_float4(l3x * mf, l3y * mf, l4x * mf, l4y * mf));
}

extern "C" void kernel_launch(void* const* d_in, const int* in_sizes, int n_in,
                              void* d_out, int out_size)
{
    const float4* in     = (const float4*)d_in[0];
    const float*  thr    = (const float*)d_in[1];
    const float4* priors = (const float4*)d_in[2];
    const float*  var    = (const float*)d_in[3];
    float* out = (float*)d_out;

    int N = in_sizes[2] / 4;  // priors is [N,4]

    int threads = 256;
    int blocks  = (N + threads - 1) / threads;
    retina_decode_kernel<<<blocks, threads>>>(in, priors, thr, var, out, N);
}

// round 6
// speedup vs baseline: 1.3538x; 1.0462x over previous
#include <cuda_runtime.h>
#include <cuda_bf16.h>

// RetinaFace decode, N = 1e6 priors. R1 structure (1 prior/thread, fully
// coalesced, default cache policy) + 128-thread blocks for finer wave
// quantization / higher occupancy + 2-class softmax as sigmoid(|c1-c0|).
//
// Output layout (float32):
//   [0    , 4N )  boxes_m    (N,4)
//   [4N   , 5N )  conf_m     (N,)
//   [5N   , 6N )  pred_m     (N,)  == 0 always (2-class)
//   [6N   , 22N)  detections (1,N,16)
//   [22N  , 23N)  keep       (N,)

__global__ __launch_bounds__(128) void retina_decode_kernel(
    const float4* __restrict__ in,      // [N,16] as float4[4N]
    const float4* __restrict__ priors,  // [N] float4
    const float* __restrict__ thr,
    const float* __restrict__ var,
    float* __restrict__ out,
    int N)
{
    int i = blockIdx.x * blockDim.x + threadIdx.x;
    if (i >= N) return;

    const float v0 = var[0];
    const float v1 = var[1];
    const float th = thr[0];

    const float4* ip = in + (size_t)4 * i;
    float4 a = ip[0];          // loc deltas
    float4 b = ip[1];          // c0, c1, lm0x, lm0y
    float4 c = ip[2];          // lm1..lm2
    float4 d = ip[3];          // lm3..lm4
    float4 p = priors[i];

    // 2-class softmax max-prob: e_max/(e0+e1) = 1/(1 + e^{-|c1-c0|}) = sigmoid(|diff|)
    // pred==1 iff c1 > c0 (jnp.argmax tie -> index 0)
    float diff = b.y - b.x;
    float conf = 1.0f / (1.0f + __expf(-fabsf(diff)));
    bool  keep = (diff > 0.0f) && (conf > th);
    float mf   = keep ? 1.0f : 0.0f;

    // box decode
    float cx = p.x + a.x * v0 * p.z;
    float cy = p.y + a.y * v0 * p.w;
    float w  = p.z * __expf(a.z * v1);
    float h  = p.w * __expf(a.w * v1);
    float x0 = cx - 0.5f * w;
    float y0 = cy - 0.5f * h;
    float x1 = x0 + w;
    float y1 = y0 + h;

    // landmarks: l = prior.xy + pt * v0 * prior.wh
    float sx = v0 * p.z, sy = v0 * p.w;
    float l0x = p.x + b.z * sx, l0y = p.y + b.w * sy;
    float l1x = p.x + c.x * sx, l1y = p.y + c.y * sy;
    float l2x = p.x + c.z * sx, l2y = p.y + c.w * sy;
    float l3x = p.x + d.x * sx, l3y = p.y + d.y * sy;
    float l4x = p.x + d.z * sx, l4y = p.y + d.w * sy;

    float4 box  = make_float4(x0 * mf, y0 * mf, x1 * mf, y1 * mf);
    float confm = conf * mf;

    size_t Ns = (size_t)N;

    reinterpret_cast<float4*>(out)[i] = box;   // boxes_m
    out[4 * Ns + i]  = confm;                  // conf_m
    out[5 * Ns + i]  = 0.0f;                   // pred_m (always 0)
    out[22 * Ns + i] = mf;                     // keep

    float4* det = reinterpret_cast<float4*>(out + 6 * Ns) + (size_t)4 * i;
    det[0] = box;
    det[1] = make_float4(confm, 0.0f, l0x * mf, l0y * mf);
    det[2] = make_float4(l1x * mf, l1y * mf, l2x * mf, l2y * mf);
    det[3] = make_float4(l3x * mf, l3y * mf, l4x * mf, l4y * mf);
}

extern "C" void kernel_launch(void* const* d_in, const int* in_sizes, int n_in,
                              void* d_out, int out_size)
{
    const float4* in     = (const float4*)d_in[0];
    const float*  thr    = (const float*)d_in[1];
    const float4* priors = (const float4*)d_in[2];
    const float*  var    = (const float*)d_in[3];
    float* out = (float*)d_out;

    int N = in_sizes[2] / 4;  // priors is [N,4]

    int threads = 128;
    int blocks  = (N + threads - 1) / threads;
    retina_decode_kernel<<<blocks, threads>>>(in, priors, thr, var, out, N);
}

// round 7
// speedup vs baseline: 1.4237x; 1.0516x over previous
#include <cuda_runtime.h>
#include <cuda_bf16.h>

// RetinaFace decode, N = 1e6 priors.
// Key fix: the [N,16] input and detections arrays were accessed with a 64B
// per-thread stride (each LDG/STG.128 wavefront touched 16 lines at 16B each).
// This version stages both through SMEM so every global LDG/STG.128 is dense
// (consecutive threads -> consecutive 16B), cutting L1 wavefronts ~3x.
//
// Output layout (float32):
//   [0    , 4N )  boxes_m    (N,4)
//   [4N   , 5N )  conf_m     (N,)
//   [5N   , 6N )  pred_m     (N,)  == 0 always (2-class)
//   [6N   , 22N)  detections (1,N,16)
//   [22N  , 23N)  keep       (N,)

__global__ __launch_bounds__(128) void retina_decode_kernel(
    const float4* __restrict__ in,      // [N,16] as float4[4N]
    const float4* __restrict__ priors,  // [N] float4
    const float* __restrict__ thr,
    const float* __restrict__ var,
    float* __restrict__ out,
    int N)
{
    // stride-5 float4 layout per prior: sbuf[5*q + r], r = 0..3 (r=4 unused pad)
    __shared__ float4 sbuf[5 * 128];

    const int tid = threadIdx.x;
    const int B0  = blockIdx.x * 128;
    const int i   = B0 + tid;

    const float v0 = var[0];
    const float v1 = var[1];
    const float th = thr[0];

    const size_t n4    = (size_t)4 * N;
    const size_t gbase = (size_t)4 * B0;

    // ---- Pass 1: dense cooperative load of input slab (128 priors x 64B) ----
    #pragma unroll
    for (int k = 0; k < 4; k++) {
        int j = k * 128 + tid;            // 0..511 local float4 index
        size_t g = gbase + j;
        if (g < n4)
            sbuf[5 * (j >> 2) + (j & 3)] = in[g];
    }
    __syncthreads();

    const bool act = (i < N);

    float4 box, d1, d2, d3;
    float confm, mf;

    if (act) {
        float4 a = sbuf[5 * tid + 0];     // loc deltas
        float4 b = sbuf[5 * tid + 1];     // c0, c1, lm0x, lm0y
        float4 c = sbuf[5 * tid + 2];     // lm1..lm2
        float4 d = sbuf[5 * tid + 3];     // lm3..lm4
        float4 p = priors[i];             // dense already

        // 2-class softmax max-prob = sigmoid(|c1-c0|); pred==1 iff c1 > c0
        float diff = b.y - b.x;
        float conf = 1.0f / (1.0f + __expf(-fabsf(diff)));
        bool  keep = (diff > 0.0f) && (conf > th);
        mf = keep ? 1.0f : 0.0f;

        float cx = p.x + a.x * v0 * p.z;
        float cy = p.y + a.y * v0 * p.w;
        float w  = p.z * __expf(a.z * v1);
        float h  = p.w * __expf(a.w * v1);
        float x0 = cx - 0.5f * w;
        float y0 = cy - 0.5f * h;
        float x1 = x0 + w;
        float y1 = y0 + h;

        float sx = v0 * p.z, sy = v0 * p.w;
        float l0x = p.x + b.z * sx, l0y = p.y + b.w * sy;
        float l1x = p.x + c.x * sx, l1y = p.y + c.y * sy;
        float l2x = p.x + c.z * sx, l2y = p.y + c.w * sy;
        float l3x = p.x + d.x * sx, l3y = p.y + d.y * sy;
        float l4x = p.x + d.z * sx, l4y = p.y + d.w * sy;

        box   = make_float4(x0 * mf, y0 * mf, x1 * mf, y1 * mf);
        confm = conf * mf;
        d1 = make_float4(confm, 0.0f, l0x * mf, l0y * mf);
        d2 = make_float4(l1x * mf, l1y * mf, l2x * mf, l2y * mf);
        d3 = make_float4(l3x * mf, l3y * mf, l4x * mf, l4y * mf);

        size_t Ns = (size_t)N;
        reinterpret_cast<float4*>(out)[i] = box;   // boxes_m (dense)
        out[4 * Ns + i]  = confm;                  // conf_m
        out[5 * Ns + i]  = 0.0f;                   // pred_m (always 0)
        out[22 * Ns + i] = mf;                     // keep
    }

    // ---- Pass 2: stage det rows, then dense cooperative store ----
    __syncthreads();   // done reading input slab from sbuf
    if (act) {
        sbuf[5 * tid + 0] = box;
        sbuf[5 * tid + 1] = d1;
        sbuf[5 * tid + 2] = d2;
        sbuf[5 * tid + 3] = d3;
    }
    __syncthreads();

    float4* det = reinterpret_cast<float4*>(out + (size_t)6 * N);
    #pragma unroll
    for (int k = 0; k < 4; k++) {
        int j = k * 128 + tid;
        size_t g = gbase + j;
        if (g < n4)
            det[g] = sbuf[5 * (j >> 2) + (j & 3)];
    }
}

extern "C" void kernel_launch(void* const* d_in, const int* in_sizes, int n_in,
                              void* d_out, int out_size)
{
    const float4* in     = (const float4*)d_in[0];
    const float*  thr    = (const float*)d_in[1];
    const float4* priors = (const float4*)d_in[2];
    const float*  var    = (const float*)d_in[3];
    float* out = (float*)d_out;

    int N = in_sizes[2] / 4;  // priors is [N,4]

    int threads = 128;
    int blocks  = (N + threads - 1) / threads;
    retina_decode_kernel<<<blocks, threads>>>(in, priors, thr, var, out, N);
}